// round 14
// baseline (speedup 1.0000x reference)
#include <cuda_runtime.h>
#include <math.h>

#define BB 4
#define NN 128
#define LL 20
#define DD 512
#define SCALE 0.044194173824159216f  // 1/sqrt(512)

// -------- scratch (device globals; no allocation allowed) --------
__device__ float g_q[BB * NN * DD];       // q projection (bias included)
__device__ float g_k[BB * LL * DD];       // k projection (bias included)
__device__ float g_fbq[BB * NN * DD];     // gated boundary features
__device__ float g_S0[BB * NN * NN];      // A_b logit partial (k 0..255)
__device__ float g_S1[BB * NN * NN];      // A_b logit partial (k 256..511)

// packed fp32x2 FMA (Blackwell FFMA2)
__device__ __forceinline__ float2 ffma2(float2 a, float2 b, float2 c) {
    float2 d;
    asm("fma.rn.f32x2 %0, %1, %2, %3;"
        : "=l"(reinterpret_cast<unsigned long long&>(d))
        : "l"(reinterpret_cast<unsigned long long&>(a)),
          "l"(reinterpret_cast<unsigned long long&>(b)),
          "l"(reinterpret_cast<unsigned long long&>(c)));
    return d;
}

// MUFU.TANH fast tanh
__device__ __forceinline__ float fast_tanh(float x) {
    float t;
    asm("tanh.approx.f32 %0, %1;" : "=f"(t) : "f"(x));
    return t;
}

// =====================================================================
// K1: fused projections  q = f_b@Wq^T+bq,  k = f_w@Wk^T+bk
// BM=64, BN=32, BK=16, 128 threads, double-buffered smem + reg prefetch.
// =====================================================================
__global__ void __launch_bounds__(128) proj_kernel(
    const float* __restrict__ Xq, const float* __restrict__ Xk,
    const float* __restrict__ Wq, const float* __restrict__ bq,
    const float* __restrict__ Wk, const float* __restrict__ bk)
{
    const int ntile = blockIdx.x, mtile = blockIdx.y;
    const float *X, *W, *bias;
    float* C;
    int Mrows, row0;
    if (mtile < 8) { X = Xq; W = Wq; bias = bq; C = g_q; Mrows = BB * NN; row0 = mtile * 64; }
    else           { X = Xk; W = Wk; bias = bk; C = g_k; Mrows = BB * LL; row0 = (mtile - 8) * 64; }
    const int n0 = ntile * 32;

    __shared__ __align__(16) float As[2][16][68];  // [buf][k][m]
    __shared__ __align__(16) float Bs[2][16][36];  // [buf][k][n]

    const int tid = threadIdx.x;        // 128
    const int tx = tid & 7;             // n = tx*4
    const int ty = tid >> 3;            // m = ty*4 (0..15)
    const int ar = tid >> 1;            // A loader row 0..63
    const int ak = (tid & 1) * 8;       // A loader k offset (2 float4)
    const int bn = tid >> 2;            // B loader n row 0..31
    const int bkk = (tid & 3) * 4;      // B loader k offset
    const bool avalid = (row0 + ar) < Mrows;

    float2 acc[2][4] = {};  // [m-pair][n]

    float4 pa0 = make_float4(0.f, 0.f, 0.f, 0.f), pa1 = pa0, pb;
    if (avalid) {
        pa0 = *(const float4*)&X[(row0 + ar) * DD + ak];
        pa1 = *(const float4*)&X[(row0 + ar) * DD + ak + 4];
    }
    pb = *(const float4*)&W[(n0 + bn) * DD + bkk];
    As[0][ak + 0][ar] = pa0.x; As[0][ak + 1][ar] = pa0.y; As[0][ak + 2][ar] = pa0.z; As[0][ak + 3][ar] = pa0.w;
    As[0][ak + 4][ar] = pa1.x; As[0][ak + 5][ar] = pa1.y; As[0][ak + 6][ar] = pa1.z; As[0][ak + 7][ar] = pa1.w;
    Bs[0][bkk + 0][bn] = pb.x; Bs[0][bkk + 1][bn] = pb.y; Bs[0][bkk + 2][bn] = pb.z; Bs[0][bkk + 3][bn] = pb.w;
    __syncthreads();

    for (int t = 0; t < 32; t++) {
        const int cur = t & 1;
        if (t < 31) {
            const int k0 = (t + 1) * 16;
            pa0 = make_float4(0.f, 0.f, 0.f, 0.f); pa1 = pa0;
            if (avalid) {
                pa0 = *(const float4*)&X[(row0 + ar) * DD + k0 + ak];
                pa1 = *(const float4*)&X[(row0 + ar) * DD + k0 + ak + 4];
            }
            pb = *(const float4*)&W[(n0 + bn) * DD + k0 + bkk];
        }

#pragma unroll
        for (int kk = 0; kk < 16; kk++) {
            const float4 a = *(const float4*)&As[cur][kk][ty * 4];
            const float4 bv = *(const float4*)&Bs[cur][kk][tx * 4];
            const float2 mp0 = make_float2(a.x, a.y);
            const float2 mp1 = make_float2(a.z, a.w);
            const float2 d0 = make_float2(bv.x, bv.x);
            const float2 d1 = make_float2(bv.y, bv.y);
            const float2 d2 = make_float2(bv.z, bv.z);
            const float2 d3 = make_float2(bv.w, bv.w);
            acc[0][0] = ffma2(mp0, d0, acc[0][0]); acc[0][1] = ffma2(mp0, d1, acc[0][1]);
            acc[0][2] = ffma2(mp0, d2, acc[0][2]); acc[0][3] = ffma2(mp0, d3, acc[0][3]);
            acc[1][0] = ffma2(mp1, d0, acc[1][0]); acc[1][1] = ffma2(mp1, d1, acc[1][1]);
            acc[1][2] = ffma2(mp1, d2, acc[1][2]); acc[1][3] = ffma2(mp1, d3, acc[1][3]);
        }
        __syncthreads();

        if (t < 31) {
            const int nxt = cur ^ 1;
            As[nxt][ak + 0][ar] = pa0.x; As[nxt][ak + 1][ar] = pa0.y;
            As[nxt][ak + 2][ar] = pa0.z; As[nxt][ak + 3][ar] = pa0.w;
            As[nxt][ak + 4][ar] = pa1.x; As[nxt][ak + 5][ar] = pa1.y;
            As[nxt][ak + 6][ar] = pa1.z; As[nxt][ak + 7][ar] = pa1.w;
            Bs[nxt][bkk + 0][bn] = pb.x; Bs[nxt][bkk + 1][bn] = pb.y;
            Bs[nxt][bkk + 2][bn] = pb.z; Bs[nxt][bkk + 3][bn] = pb.w;
            __syncthreads();
        }
    }

    const float4 bv4 = *(const float4*)&bias[n0 + tx * 4];
#pragma unroll
    for (int mp = 0; mp < 2; mp++) {
        const int r0 = row0 + ty * 4 + 2 * mp;
        if (r0 < Mrows) {
            float4 v;
            v.x = acc[mp][0].x + bv4.x; v.y = acc[mp][1].x + bv4.y;
            v.z = acc[mp][2].x + bv4.z; v.w = acc[mp][3].x + bv4.w;
            *(float4*)&C[r0 * DD + n0 + tx * 4] = v;
        }
        if (r0 + 1 < Mrows) {
            float4 v;
            v.x = acc[mp][0].y + bv4.x; v.y = acc[mp][1].y + bv4.y;
            v.z = acc[mp][2].y + bv4.z; v.w = acc[mp][3].y + bv4.w;
            *(float4*)&C[(r0 + 1) * DD + n0 + tx * 4] = v;
        }
    }
}

// =====================================================================
// K2: fused cross-attention + sentence gate.  One block per (b, n).
// =====================================================================
__global__ void __launch_bounds__(256) cross_attn_kernel(
    const float* __restrict__ f_b, const float* __restrict__ f_w,
    const float* __restrict__ f_s)
{
    const int n = blockIdx.x, b = blockIdx.y;
    __shared__ float qs[DD];
    __shared__ float logit[24];
    __shared__ float attn[24];
    const int tid = threadIdx.x;  // 256
    const int w = tid >> 5, lane = tid & 31;

    const float* qrow = &g_q[(b * NN + n) * DD];
    for (int d = tid; d < DD; d += 256) qs[d] = qrow[d];
    __syncthreads();

    for (int l = w; l < LL; l += 8) {
        const float* krow = &g_k[(b * LL + l) * DD];
        float s = 0.f;
        for (int d = lane; d < DD; d += 32) s += qs[d] * krow[d];
#pragma unroll
        for (int o = 16; o > 0; o >>= 1) s += __shfl_xor_sync(0xffffffffu, s, o);
        if (lane == 0) logit[l] = s * SCALE;
    }
    __syncthreads();

    if (tid < 32) {
        float lg = (tid < LL) ? logit[tid] : -1e30f;
        float mx = lg;
#pragma unroll
        for (int o = 16; o > 0; o >>= 1) mx = fmaxf(mx, __shfl_xor_sync(0xffffffffu, mx, o));
        float e = (tid < LL) ? __expf(lg - mx) : 0.f;
        float s = e;
#pragma unroll
        for (int o = 16; o > 0; o >>= 1) s += __shfl_xor_sync(0xffffffffu, s, o);
        if (tid < LL) attn[tid] = e / s;
    }
    __syncthreads();

    for (int d = tid; d < DD; d += 256) {
        float acc = 0.f;
#pragma unroll
        for (int l = 0; l < LL; l++) acc += attn[l] * f_w[(b * LL + l) * DD + d];
        const float v = f_b[(b * NN + n) * DD + d] * (acc + f_s[b * DD + d]);
        g_fbq[(b * NN + n) * DD + d] = v;
    }
}

// =====================================================================
// K3: A_b logit partials = scale * f_bq @ f_bq^T.  SYMMETRIC (rt<=ct),
// K-SPLIT x2, 128 threads, double-buffered, FFMA2.  Mirror stores give
// full (symmetric) S0/S1 so K4 can read columns as rows.
// =====================================================================
__global__ void __launch_bounds__(128) ab_logits_kernel()
{
    const int ct = blockIdx.x, rt = blockIdx.y;
    if (rt > ct) return;
    const int b = blockIdx.z >> 1, kz = blockIdx.z & 1;
    const float* X = &g_fbq[b * NN * DD];
    float* Sb = (kz == 0) ? &g_S0[b * NN * NN] : &g_S1[b * NN * NN];
    const int r0 = rt * 32, c0 = ct * 32;
    const int kbeg = kz * 256;

    __shared__ __align__(16) float As[2][16][36];
    __shared__ __align__(16) float Bs[2][16][36];
    const int tid = threadIdx.x;  // 128
    const int tx = tid & 7;       // n = tx*4
    const int ty = tid >> 3;      // m-pair: m = ty*2
    const int lr = tid >> 2;      // loader row 0..31
    const int lk = (tid & 3) * 4; // loader k offset

    float2 acc[4] = {};

    float4 pa = *(const float4*)&X[(r0 + lr) * DD + kbeg + lk];
    float4 pbv = *(const float4*)&X[(c0 + lr) * DD + kbeg + lk];
    As[0][lk + 0][lr] = pa.x; As[0][lk + 1][lr] = pa.y; As[0][lk + 2][lr] = pa.z; As[0][lk + 3][lr] = pa.w;
    Bs[0][lk + 0][lr] = pbv.x; Bs[0][lk + 1][lr] = pbv.y; Bs[0][lk + 2][lr] = pbv.z; Bs[0][lk + 3][lr] = pbv.w;
    __syncthreads();

    for (int t = 0; t < 16; t++) {
        const int cur = t & 1;
        if (t < 15) {
            const int k0 = kbeg + (t + 1) * 16;
            pa = *(const float4*)&X[(r0 + lr) * DD + k0 + lk];
            pbv = *(const float4*)&X[(c0 + lr) * DD + k0 + lk];
        }

#pragma unroll
        for (int kk = 0; kk < 16; kk++) {
            const float2 a = *(const float2*)&As[cur][kk][ty * 2];
            const float4 bv = *(const float4*)&Bs[cur][kk][tx * 4];
            acc[0] = ffma2(a, make_float2(bv.x, bv.x), acc[0]);
            acc[1] = ffma2(a, make_float2(bv.y, bv.y), acc[1]);
            acc[2] = ffma2(a, make_float2(bv.z, bv.z), acc[2]);
            acc[3] = ffma2(a, make_float2(bv.w, bv.w), acc[3]);
        }
        __syncthreads();

        if (t < 15) {
            const int nxt = cur ^ 1;
            As[nxt][lk + 0][lr] = pa.x; As[nxt][lk + 1][lr] = pa.y;
            As[nxt][lk + 2][lr] = pa.z; As[nxt][lk + 3][lr] = pa.w;
            Bs[nxt][lk + 0][lr] = pbv.x; Bs[nxt][lk + 1][lr] = pbv.y;
            Bs[nxt][lk + 2][lr] = pbv.z; Bs[nxt][lk + 3][lr] = pbv.w;
            __syncthreads();
        }
    }

#pragma unroll
    for (int h = 0; h < 2; h++) {
        const int row = r0 + ty * 2 + h;
        float4 o;
        o.x = (h ? acc[0].y : acc[0].x) * SCALE;
        o.y = (h ? acc[1].y : acc[1].x) * SCALE;
        o.z = (h ? acc[2].y : acc[2].x) * SCALE;
        o.w = (h ? acc[3].y : acc[3].x) * SCALE;
        *(float4*)&Sb[row * NN + c0 + tx * 4] = o;
        if (rt != ct) {
            Sb[(c0 + tx * 4 + 0) * NN + row] = o.x;
            Sb[(c0 + tx * 4 + 1) * NN + row] = o.y;
            Sb[(c0 + tx * 4 + 2) * NN + row] = o.z;
            Sb[(c0 + tx * 4 + 3) * NN + row] = o.w;
        }
    }
}

// =====================================================================
// K4: fused softmax + final, j-PAIRED.  Block (jp, b), 512 threads.
// Exploits S symmetry: column j of A == row j of S with per-row norms.
//   Phase 0a: row stats (m_i, inv_i) for all 128 rows of batch b
//             (redundant per block; L2-resident S, overlapped).
//   Phase 0b: read row j0/j1 of S once; arow = exp(v-m_j)*inv_j,
//             acol = exp(v-m_i)*inv_i  (same data, two norms).
//   Phase A (f_bb): group g sums m in [g*32,g*32+32) for BOTH j0,j1.
//   Phase B (f_bm): group g: jj=g>>1, par=g&1; MUFU.TANH sigmoid.
// =====================================================================
__global__ void __launch_bounds__(512) final_kernel(
    const float* __restrict__ f_b, const float* __restrict__ f_s,
    const float* __restrict__ f_m, float* __restrict__ out)
{
    const int jp = blockIdx.x, b = blockIdx.y;
    const int j0 = jp * 2;

    __shared__ float ms[NN], inv[NN];
    __shared__ float arow0[NN], arow1[NN], acol0[NN], acol1[NN];
    __shared__ __align__(16) float4 rA0[4][128];
    __shared__ __align__(16) float4 rA1[4][128];
    __shared__ __align__(16) float4 rB[4][128];

    const int tid = threadIdx.x;   // 512
    const int q = tid & 127;
    const int g = tid >> 7;        // group 0..3
    const int w = tid >> 5, lane = tid & 31;

    const float* S0b = &g_S0[b * NN * NN];
    const float* S1b = &g_S1[b * NN * NN];

    // ---- Phase 0a: row stats for all 128 rows (8 rows per warp) ----
#pragma unroll
    for (int r8 = 0; r8 < 8; r8++) {
        const int row = w * 8 + r8;
        const float4 s0 = *(const float4*)&S0b[row * NN + lane * 4];
        const float4 s1 = *(const float4*)&S1b[row * NN + lane * 4];
        float4 v;
        v.x = s0.x + s1.x; v.y = s0.y + s1.y; v.z = s0.z + s1.z; v.w = s0.w + s1.w;
        float m = fmaxf(fmaxf(v.x, v.y), fmaxf(v.z, v.w));
#pragma unroll
        for (int o = 16; o > 0; o >>= 1) m = fmaxf(m, __shfl_xor_sync(0xffffffffu, m, o));
        float e = __expf(v.x - m) + __expf(v.y - m) + __expf(v.z - m) + __expf(v.w - m);
#pragma unroll
        for (int o = 16; o > 0; o >>= 1) e += __shfl_xor_sync(0xffffffffu, e, o);
        if (lane == 0) { ms[row] = m; inv[row] = 1.f / e; }
    }
    __syncthreads();

    // ---- Phase 0b: row j0/j1 -> arow (row norm) + acol (per-i norm) ----
    if (tid < 256) {
        const int jj = tid >> 7;       // 0 -> j0, 1 -> j1
        const int t = tid & 127;
        const int row = j0 + jj;
        const float v = S0b[row * NN + t] + S1b[row * NN + t];
        const float ar = __expf(v - ms[row]) * inv[row];
        const float ac = __expf(v - ms[t]) * inv[t];
        if (jj == 0) { arow0[t] = ar; acol0[t] = ac; }
        else         { arow1[t] = ar; acol1[t] = ac; }
    }
    __syncthreads();

    const int d4 = q * 4;
    float4 fsh = *(const float4*)&f_s[b * DD + d4];   // halved for tanh form
    fsh.x *= 0.5f; fsh.y *= 0.5f; fsh.z *= 0.5f; fsh.w *= 0.5f;

    // ---- Phase A: f_bb partial over m-quarter, both j's ----
    float4 a0 = make_float4(0.f, 0.f, 0.f, 0.f);
    float4 a1 = a0;
    {
        const float* fbb = f_b + (size_t)b * NN * DD;
#pragma unroll 4
        for (int m = g * 32; m < g * 32 + 32; m++) {
            const float4 v = *(const float4*)&fbb[(size_t)m * DD + d4];
            const float w0 = arow0[m], w1 = arow1[m];
            a0.x += w0 * v.x; a0.y += w0 * v.y; a0.z += w0 * v.z; a0.w += w0 * v.w;
            a1.x += w1 * v.x; a1.y += w1 * v.y; a1.z += w1 * v.z; a1.w += w1 * v.w;
        }
    }

    // ---- Phase B: f_bm partial (i-parity split, one j per group) ----
    const int jj = g >> 1, par = g & 1;
    const float* ac = jj ? acol1 : acol0;
    const float* fm = f_m + ((size_t)(b * NN * NN) + j0 + jj) * DD;
    float4 bm = make_float4(0.f, 0.f, 0.f, 0.f);
#pragma unroll 4
    for (int i = par; i < NN; i += 2) {
        const float a = ac[i];
        const float4 v = *(const float4*)&fm[(size_t)i * NN * DD + d4];
        const float g0 = fmaf(0.5f, fast_tanh(v.x * fsh.x), 0.5f);
        const float g1 = fmaf(0.5f, fast_tanh(v.y * fsh.y), 0.5f);
        const float g2 = fmaf(0.5f, fast_tanh(v.z * fsh.z), 0.5f);
        const float g3 = fmaf(0.5f, fast_tanh(v.w * fsh.w), 0.5f);
        bm.x += a * g0 * v.x;
        bm.y += a * g1 * v.y;
        bm.z += a * g2 * v.z;
        bm.w += a * g3 * v.w;
    }

    rA0[g][q] = a0; rA1[g][q] = a1; rB[g][q] = bm;
    __syncthreads();

    // ---- combine + residual + store ----
    if (tid < 256) {
        const int jj2 = tid >> 7;
        const int q2 = tid & 127;
        const int dd4 = q2 * 4;
        float4 s = make_float4(0.f, 0.f, 0.f, 0.f);
#pragma unroll
        for (int gg = 0; gg < 4; gg++) {
            const float4 pa = jj2 ? rA1[gg][q2] : rA0[gg][q2];
            s.x += pa.x; s.y += pa.y; s.z += pa.z; s.w += pa.w;
        }
        const float4 b0 = rB[jj2 * 2][q2];
        const float4 b1 = rB[jj2 * 2 + 1][q2];
        const size_t o = (size_t)(b * NN + j0 + jj2) * DD;
        const float4 fb4 = *(const float4*)&f_b[o + dd4];
        float4 r;
        r.x = s.x + b0.x + b1.x + fb4.x;
        r.y = s.y + b0.y + b1.y + fb4.y;
        r.z = s.z + b0.z + b1.z + fb4.z;
        r.w = s.w + b0.w + b1.w + fb4.w;
        *(float4*)&out[o + dd4] = r;
    }
}

// =====================================================================
extern "C" void kernel_launch(void* const* d_in, const int* in_sizes, int n_in,
                              void* d_out, int out_size)
{
    const float* f_b = (const float*)d_in[0];
    const float* f_w = (const float*)d_in[1];
    const float* f_s = (const float*)d_in[2];
    const float* f_m = (const float*)d_in[3];
    const float* Wq  = (const float*)d_in[4];
    const float* bq  = (const float*)d_in[5];
    const float* Wk  = (const float*)d_in[6];
    const float* bk  = (const float*)d_in[7];
    float* out = (float*)d_out;

    proj_kernel<<<dim3(16, 10), 128>>>(f_b, f_w, Wq, bq, Wk, bk);
    cross_attn_kernel<<<dim3(NN, BB), 256>>>(f_b, f_w, f_s);
    ab_logits_kernel<<<dim3(4, 4, BB * 2), 128>>>();
    final_kernel<<<dim3(NN / 2, BB), 512>>>(f_b, f_s, f_m, out);
}

// round 15
// speedup vs baseline: 1.3708x; 1.3708x over previous
#include <cuda_runtime.h>
#include <math.h>

#define BB 4
#define NN 128
#define LL 20
#define DD 512
#define SCALE 0.044194173824159216f  // 1/sqrt(512)

// -------- scratch (device globals; no allocation allowed) --------
__device__ float g_q[BB * NN * DD];       // q projection (bias included)
__device__ float g_k[BB * LL * DD];       // k projection (bias included)
__device__ float g_fbq[BB * NN * DD];     // gated boundary features
__device__ float g_S0[BB * NN * NN];      // A_b logit partial (k 0..255)
__device__ float g_S1[BB * NN * NN];      // A_b logit partial (k 256..511)
__device__ float g_ms[BB * NN];           // softmax row max
__device__ float g_inv[BB * NN];          // softmax row 1/sum

// packed fp32x2 FMA (Blackwell FFMA2)
__device__ __forceinline__ float2 ffma2(float2 a, float2 b, float2 c) {
    float2 d;
    asm("fma.rn.f32x2 %0, %1, %2, %3;"
        : "=l"(reinterpret_cast<unsigned long long&>(d))
        : "l"(reinterpret_cast<unsigned long long&>(a)),
          "l"(reinterpret_cast<unsigned long long&>(b)),
          "l"(reinterpret_cast<unsigned long long&>(c)));
    return d;
}

// MUFU.TANH fast tanh
__device__ __forceinline__ float fast_tanh(float x) {
    float t;
    asm("tanh.approx.f32 %0, %1;" : "=f"(t) : "f"(x));
    return t;
}

// =====================================================================
// K1: fused projections  q = f_b@Wq^T+bq,  k = f_w@Wk^T+bk
// BM=64, BN=32, BK=16, 128 threads, double-buffered smem + reg prefetch.
// =====================================================================
__global__ void __launch_bounds__(128) proj_kernel(
    const float* __restrict__ Xq, const float* __restrict__ Xk,
    const float* __restrict__ Wq, const float* __restrict__ bq,
    const float* __restrict__ Wk, const float* __restrict__ bk)
{
    const int ntile = blockIdx.x, mtile = blockIdx.y;
    const float *X, *W, *bias;
    float* C;
    int Mrows, row0;
    if (mtile < 8) { X = Xq; W = Wq; bias = bq; C = g_q; Mrows = BB * NN; row0 = mtile * 64; }
    else           { X = Xk; W = Wk; bias = bk; C = g_k; Mrows = BB * LL; row0 = (mtile - 8) * 64; }
    const int n0 = ntile * 32;

    __shared__ __align__(16) float As[2][16][68];  // [buf][k][m]
    __shared__ __align__(16) float Bs[2][16][36];  // [buf][k][n]

    const int tid = threadIdx.x;        // 128
    const int tx = tid & 7;             // n = tx*4
    const int ty = tid >> 3;            // m = ty*4 (0..15)
    const int ar = tid >> 1;            // A loader row 0..63
    const int ak = (tid & 1) * 8;       // A loader k offset (2 float4)
    const int bn = tid >> 2;            // B loader n row 0..31
    const int bkk = (tid & 3) * 4;      // B loader k offset
    const bool avalid = (row0 + ar) < Mrows;

    float2 acc[2][4] = {};  // [m-pair][n]

    float4 pa0 = make_float4(0.f, 0.f, 0.f, 0.f), pa1 = pa0, pb;
    if (avalid) {
        pa0 = *(const float4*)&X[(row0 + ar) * DD + ak];
        pa1 = *(const float4*)&X[(row0 + ar) * DD + ak + 4];
    }
    pb = *(const float4*)&W[(n0 + bn) * DD + bkk];
    As[0][ak + 0][ar] = pa0.x; As[0][ak + 1][ar] = pa0.y; As[0][ak + 2][ar] = pa0.z; As[0][ak + 3][ar] = pa0.w;
    As[0][ak + 4][ar] = pa1.x; As[0][ak + 5][ar] = pa1.y; As[0][ak + 6][ar] = pa1.z; As[0][ak + 7][ar] = pa1.w;
    Bs[0][bkk + 0][bn] = pb.x; Bs[0][bkk + 1][bn] = pb.y; Bs[0][bkk + 2][bn] = pb.z; Bs[0][bkk + 3][bn] = pb.w;
    __syncthreads();

    for (int t = 0; t < 32; t++) {
        const int cur = t & 1;
        if (t < 31) {
            const int k0 = (t + 1) * 16;
            pa0 = make_float4(0.f, 0.f, 0.f, 0.f); pa1 = pa0;
            if (avalid) {
                pa0 = *(const float4*)&X[(row0 + ar) * DD + k0 + ak];
                pa1 = *(const float4*)&X[(row0 + ar) * DD + k0 + ak + 4];
            }
            pb = *(const float4*)&W[(n0 + bn) * DD + k0 + bkk];
        }

#pragma unroll
        for (int kk = 0; kk < 16; kk++) {
            const float4 a = *(const float4*)&As[cur][kk][ty * 4];
            const float4 bv = *(const float4*)&Bs[cur][kk][tx * 4];
            const float2 mp0 = make_float2(a.x, a.y);
            const float2 mp1 = make_float2(a.z, a.w);
            const float2 d0 = make_float2(bv.x, bv.x);
            const float2 d1 = make_float2(bv.y, bv.y);
            const float2 d2 = make_float2(bv.z, bv.z);
            const float2 d3 = make_float2(bv.w, bv.w);
            acc[0][0] = ffma2(mp0, d0, acc[0][0]); acc[0][1] = ffma2(mp0, d1, acc[0][1]);
            acc[0][2] = ffma2(mp0, d2, acc[0][2]); acc[0][3] = ffma2(mp0, d3, acc[0][3]);
            acc[1][0] = ffma2(mp1, d0, acc[1][0]); acc[1][1] = ffma2(mp1, d1, acc[1][1]);
            acc[1][2] = ffma2(mp1, d2, acc[1][2]); acc[1][3] = ffma2(mp1, d3, acc[1][3]);
        }
        __syncthreads();

        if (t < 31) {
            const int nxt = cur ^ 1;
            As[nxt][ak + 0][ar] = pa0.x; As[nxt][ak + 1][ar] = pa0.y;
            As[nxt][ak + 2][ar] = pa0.z; As[nxt][ak + 3][ar] = pa0.w;
            As[nxt][ak + 4][ar] = pa1.x; As[nxt][ak + 5][ar] = pa1.y;
            As[nxt][ak + 6][ar] = pa1.z; As[nxt][ak + 7][ar] = pa1.w;
            Bs[nxt][bkk + 0][bn] = pb.x; Bs[nxt][bkk + 1][bn] = pb.y;
            Bs[nxt][bkk + 2][bn] = pb.z; Bs[nxt][bkk + 3][bn] = pb.w;
            __syncthreads();
        }
    }

    const float4 bv4 = *(const float4*)&bias[n0 + tx * 4];
#pragma unroll
    for (int mp = 0; mp < 2; mp++) {
        const int r0 = row0 + ty * 4 + 2 * mp;
        if (r0 < Mrows) {
            float4 v;
            v.x = acc[mp][0].x + bv4.x; v.y = acc[mp][1].x + bv4.y;
            v.z = acc[mp][2].x + bv4.z; v.w = acc[mp][3].x + bv4.w;
            *(float4*)&C[r0 * DD + n0 + tx * 4] = v;
        }
        if (r0 + 1 < Mrows) {
            float4 v;
            v.x = acc[mp][0].y + bv4.x; v.y = acc[mp][1].y + bv4.y;
            v.z = acc[mp][2].y + bv4.z; v.w = acc[mp][3].y + bv4.w;
            *(float4*)&C[(r0 + 1) * DD + n0 + tx * 4] = v;
        }
    }
}

// =====================================================================
// K2: fused cross-attention + sentence gate.  One block per (b, n).
// =====================================================================
__global__ void __launch_bounds__(256) cross_attn_kernel(
    const float* __restrict__ f_b, const float* __restrict__ f_w,
    const float* __restrict__ f_s)
{
    const int n = blockIdx.x, b = blockIdx.y;
    __shared__ float qs[DD];
    __shared__ float logit[24];
    __shared__ float attn[24];
    const int tid = threadIdx.x;  // 256
    const int w = tid >> 5, lane = tid & 31;

    const float* qrow = &g_q[(b * NN + n) * DD];
    for (int d = tid; d < DD; d += 256) qs[d] = qrow[d];
    __syncthreads();

    for (int l = w; l < LL; l += 8) {
        const float* krow = &g_k[(b * LL + l) * DD];
        float s = 0.f;
        for (int d = lane; d < DD; d += 32) s += qs[d] * krow[d];
#pragma unroll
        for (int o = 16; o > 0; o >>= 1) s += __shfl_xor_sync(0xffffffffu, s, o);
        if (lane == 0) logit[l] = s * SCALE;
    }
    __syncthreads();

    if (tid < 32) {
        float lg = (tid < LL) ? logit[tid] : -1e30f;
        float mx = lg;
#pragma unroll
        for (int o = 16; o > 0; o >>= 1) mx = fmaxf(mx, __shfl_xor_sync(0xffffffffu, mx, o));
        float e = (tid < LL) ? __expf(lg - mx) : 0.f;
        float s = e;
#pragma unroll
        for (int o = 16; o > 0; o >>= 1) s += __shfl_xor_sync(0xffffffffu, s, o);
        if (tid < LL) attn[tid] = e / s;
    }
    __syncthreads();

    for (int d = tid; d < DD; d += 256) {
        float acc = 0.f;
#pragma unroll
        for (int l = 0; l < LL; l++) acc += attn[l] * f_w[(b * LL + l) * DD + d];
        const float v = f_b[(b * NN + n) * DD + d] * (acc + f_s[b * DD + d]);
        g_fbq[(b * NN + n) * DD + d] = v;
    }
}

// =====================================================================
// K3: A_b logit partials = scale * f_bq @ f_bq^T.  SYMMETRIC (rt<=ct),
// K-SPLIT x2, 128 threads, double-buffered, FFMA2.  Mirror stores give
// full (symmetric) S0/S1 so K5 can read columns as rows.
// =====================================================================
__global__ void __launch_bounds__(128) ab_logits_kernel()
{
    const int ct = blockIdx.x, rt = blockIdx.y;
    if (rt > ct) return;
    const int b = blockIdx.z >> 1, kz = blockIdx.z & 1;
    const float* X = &g_fbq[b * NN * DD];
    float* Sb = (kz == 0) ? &g_S0[b * NN * NN] : &g_S1[b * NN * NN];
    const int r0 = rt * 32, c0 = ct * 32;
    const int kbeg = kz * 256;

    __shared__ __align__(16) float As[2][16][36];
    __shared__ __align__(16) float Bs[2][16][36];
    const int tid = threadIdx.x;  // 128
    const int tx = tid & 7;       // n = tx*4
    const int ty = tid >> 3;      // m-pair: m = ty*2
    const int lr = tid >> 2;      // loader row 0..31
    const int lk = (tid & 3) * 4; // loader k offset

    float2 acc[4] = {};

    float4 pa = *(const float4*)&X[(r0 + lr) * DD + kbeg + lk];
    float4 pbv = *(const float4*)&X[(c0 + lr) * DD + kbeg + lk];
    As[0][lk + 0][lr] = pa.x; As[0][lk + 1][lr] = pa.y; As[0][lk + 2][lr] = pa.z; As[0][lk + 3][lr] = pa.w;
    Bs[0][lk + 0][lr] = pbv.x; Bs[0][lk + 1][lr] = pbv.y; Bs[0][lk + 2][lr] = pbv.z; Bs[0][lk + 3][lr] = pbv.w;
    __syncthreads();

    for (int t = 0; t < 16; t++) {
        const int cur = t & 1;
        if (t < 15) {
            const int k0 = kbeg + (t + 1) * 16;
            pa = *(const float4*)&X[(r0 + lr) * DD + k0 + lk];
            pbv = *(const float4*)&X[(c0 + lr) * DD + k0 + lk];
        }

#pragma unroll
        for (int kk = 0; kk < 16; kk++) {
            const float2 a = *(const float2*)&As[cur][kk][ty * 2];
            const float4 bv = *(const float4*)&Bs[cur][kk][tx * 4];
            acc[0] = ffma2(a, make_float2(bv.x, bv.x), acc[0]);
            acc[1] = ffma2(a, make_float2(bv.y, bv.y), acc[1]);
            acc[2] = ffma2(a, make_float2(bv.z, bv.z), acc[2]);
            acc[3] = ffma2(a, make_float2(bv.w, bv.w), acc[3]);
        }
        __syncthreads();

        if (t < 15) {
            const int nxt = cur ^ 1;
            As[nxt][lk + 0][lr] = pa.x; As[nxt][lk + 1][lr] = pa.y;
            As[nxt][lk + 2][lr] = pa.z; As[nxt][lk + 3][lr] = pa.w;
            Bs[nxt][lk + 0][lr] = pbv.x; Bs[nxt][lk + 1][lr] = pbv.y;
            Bs[nxt][lk + 2][lr] = pbv.z; Bs[nxt][lk + 3][lr] = pbv.w;
            __syncthreads();
        }
    }

#pragma unroll
    for (int h = 0; h < 2; h++) {
        const int row = r0 + ty * 2 + h;
        float4 o;
        o.x = (h ? acc[0].y : acc[0].x) * SCALE;
        o.y = (h ? acc[1].y : acc[1].x) * SCALE;
        o.z = (h ? acc[2].y : acc[2].x) * SCALE;
        o.w = (h ? acc[3].y : acc[3].x) * SCALE;
        *(float4*)&Sb[row * NN + c0 + tx * 4] = o;
        if (rt != ct) {
            Sb[(c0 + tx * 4 + 0) * NN + row] = o.x;
            Sb[(c0 + tx * 4 + 1) * NN + row] = o.y;
            Sb[(c0 + tx * 4 + 2) * NN + row] = o.z;
            Sb[(c0 + tx * 4 + 3) * NN + row] = o.w;
        }
    }
}

// =====================================================================
// K4: softmax ROW STATS only (m_i, 1/sum_i) -> g_ms, g_inv.  4 KB out.
// Warp per row; 64 blocks x 256 threads.
// =====================================================================
__global__ void __launch_bounds__(256) stats_kernel()
{
    const int w = threadIdx.x >> 5, lane = threadIdx.x & 31;
    const int r = blockIdx.x * 8 + w;        // global row 0..511

    const float4 s0 = *(const float4*)&g_S0[r * NN + lane * 4];
    const float4 s1 = *(const float4*)&g_S1[r * NN + lane * 4];
    float4 v;
    v.x = s0.x + s1.x; v.y = s0.y + s1.y; v.z = s0.z + s1.z; v.w = s0.w + s1.w;

    float m = fmaxf(fmaxf(v.x, v.y), fmaxf(v.z, v.w));
#pragma unroll
    for (int o = 16; o > 0; o >>= 1) m = fmaxf(m, __shfl_xor_sync(0xffffffffu, m, o));
    float e = __expf(v.x - m) + __expf(v.y - m) + __expf(v.z - m) + __expf(v.w - m);
#pragma unroll
    for (int o = 16; o > 0; o >>= 1) e += __shfl_xor_sync(0xffffffffu, e, o);
    if (lane == 0) { g_ms[r] = m; g_inv[r] = 1.f / e; }
}

// =====================================================================
// K5: fused final, j-PAIRED.  Block (jp, b), 512 threads.
// S symmetry: A[i][j] = exp(S[j][i]-m_i)*inv_i (column = row reindexed).
//   Phase 0: read S row j0/j1 once + global stats -> arow*, acol*.
//   Phase A (f_bb): group g sums m in [g*32,g*32+32) for BOTH j0,j1.
//   Phase B (f_bm): group g: jj=g>>1, par=g&1; MUFU.TANH; unroll 8.
// =====================================================================
__global__ void __launch_bounds__(512) final_kernel(
    const float* __restrict__ f_b, const float* __restrict__ f_s,
    const float* __restrict__ f_m, float* __restrict__ out)
{
    const int jp = blockIdx.x, b = blockIdx.y;
    const int j0 = jp * 2;

    __shared__ float arow0[NN], arow1[NN], acol0[NN], acol1[NN];
    __shared__ __align__(16) float4 rA0[4][128];
    __shared__ __align__(16) float4 rA1[4][128];
    __shared__ __align__(16) float4 rB[4][128];

    const int tid = threadIdx.x;   // 512
    const int q = tid & 127;
    const int g = tid >> 7;        // group 0..3

    const float* S0b = &g_S0[b * NN * NN];
    const float* S1b = &g_S1[b * NN * NN];

    // ---- Phase 0: row j0/j1 + precomputed stats -> arow, acol ----
    if (tid < 256) {
        const int jj = tid >> 7;       // 0 -> j0, 1 -> j1
        const int t = tid & 127;
        const int row = j0 + jj;
        const float v = S0b[row * NN + t] + S1b[row * NN + t];
        const float ar = __expf(v - g_ms[b * NN + row]) * g_inv[b * NN + row];
        const float ac = __expf(v - g_ms[b * NN + t]) * g_inv[b * NN + t];
        if (jj == 0) { arow0[t] = ar; acol0[t] = ac; }
        else         { arow1[t] = ar; acol1[t] = ac; }
    }
    __syncthreads();

    const int d4 = q * 4;
    float4 fsh = *(const float4*)&f_s[b * DD + d4];   // halved for tanh form
    fsh.x *= 0.5f; fsh.y *= 0.5f; fsh.z *= 0.5f; fsh.w *= 0.5f;

    // ---- Phase A: f_bb partial over m-quarter, both j's ----
    float4 a0 = make_float4(0.f, 0.f, 0.f, 0.f);
    float4 a1 = a0;
    {
        const float* fbb = f_b + (size_t)b * NN * DD;
#pragma unroll 4
        for (int m = g * 32; m < g * 32 + 32; m++) {
            const float4 v = *(const float4*)&fbb[(size_t)m * DD + d4];
            const float w0 = arow0[m], w1 = arow1[m];
            a0.x += w0 * v.x; a0.y += w0 * v.y; a0.z += w0 * v.z; a0.w += w0 * v.w;
            a1.x += w1 * v.x; a1.y += w1 * v.y; a1.z += w1 * v.z; a1.w += w1 * v.w;
        }
    }

    // ---- Phase B: f_bm partial (i-parity split, one j per group) ----
    const int jj = g >> 1, par = g & 1;
    const float* ac = jj ? acol1 : acol0;
    const float* fm = f_m + ((size_t)(b * NN * NN) + j0 + jj) * DD;
    float4 bm = make_float4(0.f, 0.f, 0.f, 0.f);
#pragma unroll 8
    for (int i = par; i < NN; i += 2) {
        const float a = ac[i];
        const float4 v = *(const float4*)&fm[(size_t)i * NN * DD + d4];
        const float g0 = fmaf(0.5f, fast_tanh(v.x * fsh.x), 0.5f);
        const float g1 = fmaf(0.5f, fast_tanh(v.y * fsh.y), 0.5f);
        const float g2 = fmaf(0.5f, fast_tanh(v.z * fsh.z), 0.5f);
        const float g3 = fmaf(0.5f, fast_tanh(v.w * fsh.w), 0.5f);
        bm.x += a * g0 * v.x;
        bm.y += a * g1 * v.y;
        bm.z += a * g2 * v.z;
        bm.w += a * g3 * v.w;
    }

    rA0[g][q] = a0; rA1[g][q] = a1; rB[g][q] = bm;
    __syncthreads();

    // ---- combine + residual + store ----
    if (tid < 256) {
        const int jj2 = tid >> 7;
        const int q2 = tid & 127;
        const int dd4 = q2 * 4;
        float4 s = make_float4(0.f, 0.f, 0.f, 0.f);
#pragma unroll
        for (int gg = 0; gg < 4; gg++) {
            const float4 pa = jj2 ? rA1[gg][q2] : rA0[gg][q2];
            s.x += pa.x; s.y += pa.y; s.z += pa.z; s.w += pa.w;
        }
        const float4 b0 = rB[jj2 * 2][q2];
        const float4 b1 = rB[jj2 * 2 + 1][q2];
        const size_t o = (size_t)(b * NN + j0 + jj2) * DD;
        const float4 fb4 = *(const float4*)&f_b[o + dd4];
        float4 r;
        r.x = s.x + b0.x + b1.x + fb4.x;
        r.y = s.y + b0.y + b1.y + fb4.y;
        r.z = s.z + b0.z + b1.z + fb4.z;
        r.w = s.w + b0.w + b1.w + fb4.w;
        *(float4*)&out[o + dd4] = r;
    }
}

// =====================================================================
extern "C" void kernel_launch(void* const* d_in, const int* in_sizes, int n_in,
                              void* d_out, int out_size)
{
    const float* f_b = (const float*)d_in[0];
    const float* f_w = (const float*)d_in[1];
    const float* f_s = (const float*)d_in[2];
    const float* f_m = (const float*)d_in[3];
    const float* Wq  = (const float*)d_in[4];
    const float* bq  = (const float*)d_in[5];
    const float* Wk  = (const float*)d_in[6];
    const float* bk  = (const float*)d_in[7];
    float* out = (float*)d_out;

    proj_kernel<<<dim3(16, 10), 128>>>(f_b, f_w, Wq, bq, Wk, bk);
    cross_attn_kernel<<<dim3(NN, BB), 256>>>(f_b, f_w, f_s);
    ab_logits_kernel<<<dim3(4, 4, BB * 2), 128>>>();
    stats_kernel<<<64, 256>>>();
    final_kernel<<<dim3(NN / 2, BB), 512>>>(f_b, f_s, f_m, out);
}